// round 1
// baseline (speedup 1.0000x reference)
#include <cuda_runtime.h>
#include <math.h>

#define T_STEPS   8192
#define N_RES     2048
#define DIN       64
#define DOUT      64
#define NNZ_CAP   384          // mean nnz/row ~205, +13σ headroom, mult of 128
#define GRID_MAIN 128
#define ROWS_PER_CTA 16        // 2048 / 128
#define THREADS_MAIN 512       // 16 warps, 1 warp per row
#define LEAK      0.3f
#define ONE_MINUS_LEAK 0.7f
#define NOISE_SCL 0.01f

// ---- device scratch (static; no allocation anywhere) ----
__device__ float    g_vals[(size_t)N_RES * NNZ_CAP];          // 3.1 MB
__device__ int      g_cols[(size_t)N_RES * NNZ_CAP];          // 3.1 MB
__device__ float    g_states[(size_t)T_STEPS * N_RES];        // 64 MB (states == exchange buffer)
__device__ volatile unsigned g_flags[GRID_MAIN * 8];          // padded flags (32B apart)

// ---- reset barrier flags (runs first on every graph replay) ----
__global__ void k_init() {
    int i = threadIdx.x;
    if (i < GRID_MAIN * 8) g_flags[i] = 0u;
}

// ---- build padded sparse rows of W: one warp per row, order-preserving compaction ----
__global__ void k_build(const float* __restrict__ W) {
    int warp = (blockIdx.x * blockDim.x + threadIdx.x) >> 5;
    int lane = threadIdx.x & 31;
    if (warp >= N_RES) return;
    const float* wr = W + (size_t)warp * N_RES;
    float* vd = g_vals + (size_t)warp * NNZ_CAP;
    int*   cd = g_cols + (size_t)warp * NNZ_CAP;
    int count = 0;
    for (int base = 0; base < N_RES; base += 32) {
        float v = wr[base + lane];
        unsigned m = __ballot_sync(0xffffffffu, v != 0.0f);
        if (v != 0.0f) {
            int idx = count + __popc(m & ((1u << lane) - 1u));
            if (idx < NNZ_CAP) { vd[idx] = v; cd[idx] = base + lane; }
        }
        count += __popc(m);
    }
    if (count > NNZ_CAP) count = NNZ_CAP;   // statistically impossible; defensive
    // zero-pad: padded entries do 0.0f * s[0] == exact 0
    for (int i = count + lane; i < NNZ_CAP; i += 32) { vd[i] = 0.0f; cd[i] = 0; }
}

// ---- persistent recurrence kernel: 128 CTAs, grid-wide flag barrier each step ----
__global__ void __launch_bounds__(THREADS_MAIN, 1)
k_reservoir(const float* __restrict__ u,
            const float* __restrict__ noise,
            const float* __restrict__ W_in) {
    __shared__ float s_smem[N_RES];       // full state, refreshed every step
    __shared__ float u_s[2][DIN];         // double-buffered input vector

    const int tid  = threadIdx.x;
    const int lane = tid & 31;
    const int w    = tid >> 5;                        // warp id = local row
    const int row  = blockIdx.x * ROWS_PER_CTA + w;   // global reservoir row

    // --- park this row's sparse slice in registers for the whole run ---
    float4 v4[3]; int4 c4[3];
    {
        const float4* vp = (const float4*)(g_vals + (size_t)row * NNZ_CAP);
        const int4*   cp = (const int4*)  (g_cols + (size_t)row * NNZ_CAP);
        #pragma unroll
        for (int c = 0; c < 3; c++) { v4[c] = vp[c * 32 + lane]; c4[c] = cp[c * 32 + lane]; }
    }
    const float win0 = W_in[row * DIN + lane];
    const float win1 = W_in[row * DIN + 32 + lane];

    // --- init: s0 = 0, u[0] staged, noise[0][row] in reg ---
    for (int i = tid; i < N_RES; i += THREADS_MAIN) s_smem[i] = 0.0f;
    if (tid < DIN) u_s[0][tid] = u[tid];
    float noise_cur = noise[row];
    float noise_next = 0.0f;
    __syncthreads();

    for (int t = 0; t < T_STEPS; t++) {
        const int buf = t & 1;
        const int tn  = (t + 1 < T_STEPS) ? t + 1 : t;

        // prefetch next step inputs (latency hidden behind compute + barrier)
        if (tid < DIN) u_s[buf ^ 1][tid] = u[tn * DIN + tid];
        if (lane == 0) noise_next = noise[(size_t)tn * N_RES + row];

        // drive (W_in · u_t distributed over lanes) + sparse W·s gathers
        float acc = fmaf(win0, u_s[buf][lane], win1 * u_s[buf][lane + 32]);
        #pragma unroll
        for (int c = 0; c < 3; c++) {
            acc = fmaf(v4[c].x, s_smem[c4[c].x], acc);
            acc = fmaf(v4[c].y, s_smem[c4[c].y], acc);
            acc = fmaf(v4[c].z, s_smem[c4[c].z], acc);
            acc = fmaf(v4[c].w, s_smem[c4[c].w], acc);
        }
        #pragma unroll
        for (int o = 16; o; o >>= 1) acc += __shfl_xor_sync(0xffffffffu, acc, o);

        if (lane == 0) {
            acc += NOISE_SCL * noise_cur;
            float sold = s_smem[row];
            float snew = ONE_MINUS_LEAK * sold + LEAK * tanhf(acc);
            g_states[(size_t)t * N_RES + row] = snew;
        }
        noise_cur = noise_next;

        // ---- grid barrier: per-CTA release flag, distributed polling ----
        __syncthreads();                       // all 16 STGs of this CTA issued
        const unsigned target = (unsigned)(t + 1);
        if (tid == 0) {
            __threadfence();                   // make state stores device-visible
            g_flags[blockIdx.x * 8] = target;  // volatile release flag
        }
        if (tid < GRID_MAIN) {
            while (g_flags[tid * 8] < target) { /* spin through L2 */ }
        }
        __syncthreads();

        // ---- reload full new state s_{t+1} (written once this launch -> L2-fresh) ----
        const float4* sp = (const float4*)(g_states + (size_t)t * N_RES);
        float4 sv = __ldcg(&sp[tid]);          // 512 threads x 16B = 2048 floats
        ((float4*)s_smem)[tid] = sv;
        __syncthreads();
    }
}

// ---- readout GEMM: out[T,64] = states @ w_out^T + b_out ----
#define KC 32
__global__ void __launch_bounds__(256, 1)
k_out(const float* __restrict__ w_out, const float* __restrict__ b_out,
      float* __restrict__ out) {
    __shared__ float sA[64][KC];   // states tile [trow][kk]
    __shared__ float sB[64][KC];   // w_out tile  [d][kk]
    const int tid = threadIdx.x;
    const int tx  = tid & 15;      // 4 output cols each
    const int ty  = tid >> 4;      // 4 output rows each
    const int t0  = blockIdx.x * 64;

    float acc[4][4];
    #pragma unroll
    for (int i = 0; i < 4; i++)
        #pragma unroll
        for (int j = 0; j < 4; j++) acc[i][j] = 0.0f;

    for (int k0 = 0; k0 < N_RES; k0 += KC) {
        #pragma unroll
        for (int it = 0; it < 2; it++) {
            int idx = tid + it * 256;          // 512 float4 slots (64 rows x 8)
            int r  = idx >> 3;
            int kk = (idx & 7) * 4;
            *(float4*)&sA[r][kk] = *(const float4*)&g_states[(size_t)(t0 + r) * N_RES + k0 + kk];
            *(float4*)&sB[r][kk] = *(const float4*)&w_out[(size_t)r * N_RES + k0 + kk];
        }
        __syncthreads();
        #pragma unroll
        for (int kk = 0; kk < KC; kk += 4) {
            float4 a[4], b[4];
            #pragma unroll
            for (int i = 0; i < 4; i++) a[i] = *(const float4*)&sA[ty * 4 + i][kk];
            #pragma unroll
            for (int j = 0; j < 4; j++) b[j] = *(const float4*)&sB[tx * 4 + j][kk];
            #pragma unroll
            for (int i = 0; i < 4; i++)
                #pragma unroll
                for (int j = 0; j < 4; j++) {
                    acc[i][j] = fmaf(a[i].x, b[j].x, acc[i][j]);
                    acc[i][j] = fmaf(a[i].y, b[j].y, acc[i][j]);
                    acc[i][j] = fmaf(a[i].z, b[j].z, acc[i][j]);
                    acc[i][j] = fmaf(a[i].w, b[j].w, acc[i][j]);
                }
        }
        __syncthreads();
    }
    #pragma unroll
    for (int i = 0; i < 4; i++)
        #pragma unroll
        for (int j = 0; j < 4; j++)
            out[(size_t)(t0 + ty * 4 + i) * DOUT + tx * 4 + j] = acc[i][j] + b_out[tx * 4 + j];
}

extern "C" void kernel_launch(void* const* d_in, const int* in_sizes, int n_in,
                              void* d_out, int out_size) {
    const float* u     = (const float*)d_in[0];
    const float* noise = (const float*)d_in[1];
    const float* W_in  = (const float*)d_in[2];
    const float* W     = (const float*)d_in[3];
    const float* w_out = (const float*)d_in[4];
    const float* b_out = (const float*)d_in[5];
    float* out = (float*)d_out;

    k_init<<<1, 1024>>>();
    k_build<<<64, 1024>>>(W);                      // 2048 warps, one per row
    k_reservoir<<<GRID_MAIN, THREADS_MAIN>>>(u, noise, W_in);
    k_out<<<T_STEPS / 64, 256>>>(w_out, b_out, out);
}